// round 7
// baseline (speedup 1.0000x reference)
#include <cuda_runtime.h>
#include <math.h>

// Chamfer distance, B=4, N=M=8192, 3D — SYMMETRIC single-evaluation version.
// d matrix computed ONCE per pair; row-mins (dist1) and col-mins (dist2) both
// harvested. Argmins deferred via u64 keys (dist_bits<<32 | group_base):
// d >= 0 so float bit order == unsigned order; u64 min = lexicographic
// (dist, group) min = exact first-occurrence tie-break. Finalize kernel
// recomputes the winning group with IDENTICAL packed ops and recovers the
// in-group index from its own registers (no cross-path bit matching).
//
// d_out (float32): dist1[B*N] | dist2[B*M] | idx1[B*N] | idx2[B*M]

#define BATCH 4
#define NPTS  8192
#define TR 128          // tile rows (xyz1 points)
#define TC 128          // tile cols (xyz2 points)
#define TB 128          // threads per tile block: 16 (tx) x 8 (ty)
#define RPT 16          // rows per thread
#define CPT 8           // cols per thread

typedef unsigned long long u64;
typedef unsigned int u32;

__device__ u64 g_row[BATCH * NPTS];   // per xyz1 point: (best_d_bits<<32)|colgroup
__device__ u64 g_col[BATCH * NPTS];   // per xyz2 point: (best_d_bits<<32)|rowgroup

__device__ __forceinline__ void unpack2(float& lo, float& hi, u64 v) {
    asm("mov.b64 {%0, %1}, %2;" : "=f"(lo), "=f"(hi) : "l"(v));
}
__device__ __forceinline__ u64 pack2(float lo, float hi) {
    u64 r;
    asm("mov.b64 %0, {%1, %2};" : "=l"(r) : "f"(lo), "f"(hi));
    return r;
}
__device__ __forceinline__ u64 add2(u64 a, u64 b) {
    u64 r;
    asm("add.rn.f32x2 %0, %1, %2;" : "=l"(r) : "l"(a), "l"(b));
    return r;
}
__device__ __forceinline__ u64 mul2(u64 a, u64 b) {
    u64 r;
    asm("mul.rn.f32x2 %0, %1, %2;" : "=l"(r) : "l"(a), "l"(b));
    return r;
}
__device__ __forceinline__ float negf(float x) {
    return __int_as_float(__float_as_int(x) ^ 0x80000000);
}
__device__ __forceinline__ u64 mkkey(float d, u32 g) {
    return ((u64)(u32)__float_as_int(d) << 32) | g;
}

// ---------------------------------------------------------------- init
__global__ void init_kernel() {
    int i = blockIdx.x * blockDim.x + threadIdx.x;
    if (i < BATCH * NPTS) {
        g_row[i] = ~0ull;
        g_col[i] = ~0ull;
    }
}

// ---------------------------------------------------------------- tiles
__global__ __launch_bounds__(TB) void tile_kernel(
    const float* __restrict__ xyz1,
    const float* __restrict__ xyz2)
{
    __shared__ __align__(16) float sr[3][TR];   // raw row coords (xyz1)
    __shared__ __align__(16) float sc[3][TC];   // NEGATED col coords (xyz2)
    __shared__ u64 srow[TR][16];                // per-row keys by tx
    __shared__ u64 scol[TC][8];                 // per-col keys by ty

    const int b       = blockIdx.z;
    const int rowbase = blockIdx.y * TR;
    const int colbase = blockIdx.x * TC;
    const int tid = threadIdx.x;
    const int tx  = tid & 15;       // col group: cols tx*8 .. tx*8+7
    const int ty  = tid >> 4;       // row group: rows ty*16 .. ty*16+15

    // Stage tile coords (one row pt + one col pt per thread).
    {
        const float* p1 = xyz1 + ((size_t)b * NPTS + rowbase + tid) * 3;
        const float* p2 = xyz2 + ((size_t)b * NPTS + colbase + tid) * 3;
        sr[0][tid] = p1[0];
        sr[1][tid] = p1[1];
        sr[2][tid] = p1[2];
        sc[0][tid] = negf(p2[0]);
        sc[1][tid] = negf(p2[1]);
        sc[2][tid] = negf(p2[2]);
    }
    __syncthreads();

    // This thread's 8 negated col coords, packed as 4 f32x2 per coord.
    u64 cx[4], cy[4], cz[4];
    {
        const ulonglong2* vx = (const ulonglong2*)(&sc[0][tx * CPT]);
        const ulonglong2* vy = (const ulonglong2*)(&sc[1][tx * CPT]);
        const ulonglong2* vz = (const ulonglong2*)(&sc[2][tx * CPT]);
        ulonglong2 a, c;
        a = vx[0]; c = vx[1]; cx[0] = a.x; cx[1] = a.y; cx[2] = c.x; cx[3] = c.y;
        a = vy[0]; c = vy[1]; cy[0] = a.x; cy[1] = a.y; cy[2] = c.x; cy[3] = c.y;
        a = vz[0]; c = vz[1]; cz[0] = a.x; cz[1] = a.y; cz[2] = c.x; cz[3] = c.y;
    }

    float colmin[CPT];
    #pragma unroll
    for (int k = 0; k < CPT; ++k) colmin[k] = INFINITY;

    const u32 colgroup = (u32)(colbase + tx * CPT);
    const u32 rowgroup = (u32)(rowbase + ty * RPT);

    #pragma unroll 4
    for (int ri = 0; ri < RPT; ++ri) {
        const int r = ty * RPT + ri;
        const u64 pxx = pack2(sr[0][r], sr[0][r]);
        const u64 pyy = pack2(sr[1][r], sr[1][r]);
        const u64 pzz = pack2(sr[2][r], sr[2][r]);

        // d = ((dx*dx + dy*dy) + dz*dz), per-lane rn, NO FMA (matches XLA).
        u64 d01, d23, d45, d67;
        {
            u64 dx0 = add2(pxx, cx[0]), dx1 = add2(pxx, cx[1]);
            u64 dx2 = add2(pxx, cx[2]), dx3 = add2(pxx, cx[3]);
            u64 dy0 = add2(pyy, cy[0]), dy1 = add2(pyy, cy[1]);
            u64 dy2 = add2(pyy, cy[2]), dy3 = add2(pyy, cy[3]);
            u64 dz0 = add2(pzz, cz[0]), dz1 = add2(pzz, cz[1]);
            u64 dz2 = add2(pzz, cz[2]), dz3 = add2(pzz, cz[3]);
            d01 = add2(add2(mul2(dx0, dx0), mul2(dy0, dy0)), mul2(dz0, dz0));
            d23 = add2(add2(mul2(dx1, dx1), mul2(dy1, dy1)), mul2(dz1, dz1));
            d45 = add2(add2(mul2(dx2, dx2), mul2(dy2, dy2)), mul2(dz2, dz2));
            d67 = add2(add2(mul2(dx3, dx3), mul2(dy3, dy3)), mul2(dz3, dz3));
        }

        float d0, d1, d2, d3, d4, d5, d6, d7;
        unpack2(d0, d1, d01);
        unpack2(d2, d3, d23);
        unpack2(d4, d5, d45);
        unpack2(d6, d7, d67);

        // Column running mins (value only; row recovered in finalize).
        colmin[0] = fminf(colmin[0], d0);
        colmin[1] = fminf(colmin[1], d1);
        colmin[2] = fminf(colmin[2], d2);
        colmin[3] = fminf(colmin[3], d3);
        colmin[4] = fminf(colmin[4], d4);
        colmin[5] = fminf(colmin[5], d5);
        colmin[6] = fminf(colmin[6], d6);
        colmin[7] = fminf(colmin[7], d7);

        // Row min over this thread's 8 cols -> deferred key.
        const float m = fminf(fminf(fminf(d0, d1), fminf(d2, d3)),
                              fminf(fminf(d4, d5), fminf(d6, d7)));
        srow[r][tx] = mkkey(m, colgroup);
    }

    // Column keys.
    #pragma unroll
    for (int k = 0; k < CPT; ++k)
        scol[tx * CPT + k][ty] = mkkey(colmin[k], rowgroup);

    __syncthreads();

    // Block-level reductions + one global RED per row / col.
    {
        u64 v = srow[tid][0];
        #pragma unroll
        for (int i = 1; i < 16; ++i) v = (srow[tid][i] < v) ? srow[tid][i] : v;
        atomicMin(&g_row[(size_t)b * NPTS + rowbase + tid], v);
    }
    {
        u64 v = scol[tid][0];
        #pragma unroll
        for (int i = 1; i < 8; ++i) v = (scol[tid][i] < v) ? scol[tid][i] : v;
        atomicMin(&g_col[(size_t)b * NPTS + colbase + tid], v);
    }
}

// ---------------------------------------------------------------- finalize
// Recompute the winning group's distances with the SAME packed ops and
// recover the in-group argmin from those registers (first occurrence).
__global__ __launch_bounds__(128) void finalize_kernel(
    const float* __restrict__ xyz1,
    const float* __restrict__ xyz2,
    float* __restrict__ out)
{
    const int idx = blockIdx.x * 128 + threadIdx.x;   // 0 .. 65535
    const int half = BATCH * NPTS;                    // 32768

    if (idx < half) {
        // Row side: dist1/idx1 for xyz1 point (b, r), candidates = xyz2.
        const int b = idx >> 13, r = idx & (NPTS - 1);
        const u64 key = g_row[idx];
        const u32 j0  = (u32)key;    // winning col group base (multiple of 8)

        const float* p = xyz1 + ((size_t)b * NPTS + r) * 3;
        const u64 pxx = pack2(p[0], p[0]);
        const u64 pyy = pack2(p[1], p[1]);
        const u64 pzz = pack2(p[2], p[2]);

        float d[8];
        #pragma unroll
        for (int kk = 0; kk < 4; ++kk) {
            const float* c0 = xyz2 + ((size_t)b * NPTS + j0 + 2 * kk) * 3;
            const float* c1 = c0 + 3;
            u64 dxx = add2(pxx, pack2(negf(c0[0]), negf(c1[0])));
            u64 dyy = add2(pyy, pack2(negf(c0[1]), negf(c1[1])));
            u64 dzz = add2(pzz, pack2(negf(c0[2]), negf(c1[2])));
            u64 dd  = add2(add2(mul2(dxx, dxx), mul2(dyy, dyy)), mul2(dzz, dzz));
            unpack2(d[2 * kk], d[2 * kk + 1], dd);
        }
        const float m = fminf(fminf(fminf(d[0], d[1]), fminf(d[2], d[3])),
                              fminf(fminf(d[4], d[5]), fminf(d[6], d[7])));
        int s = 7;                        // descending scan: lowest match wins
        if (d[6] == m) s = 6;
        if (d[5] == m) s = 5;
        if (d[4] == m) s = 4;
        if (d[3] == m) s = 3;
        if (d[2] == m) s = 2;
        if (d[1] == m) s = 1;
        if (d[0] == m) s = 0;

        out[idx]            = m;                      // dist1
        out[2 * half + idx] = (float)(j0 + s);        // idx1
    } else {
        // Col side: dist2/idx2 for xyz2 point (b, j), candidates = xyz1.
        const int o = idx - half;
        const int b = o >> 13, j = o & (NPTS - 1);
        const u64 key = g_col[o];
        const u32 r0  = (u32)key;    // winning row group base (multiple of 16)

        const float* c = xyz2 + ((size_t)b * NPTS + j) * 3;
        const u64 ncx = pack2(negf(c[0]), negf(c[0]));
        const u64 ncy = pack2(negf(c[1]), negf(c[1]));
        const u64 ncz = pack2(negf(c[2]), negf(c[2]));

        float d[16];
        #pragma unroll
        for (int kk = 0; kk < 8; ++kk) {
            const float* p0 = xyz1 + ((size_t)b * NPTS + r0 + 2 * kk) * 3;
            const float* p1 = p0 + 3;
            u64 dxx = add2(pack2(p0[0], p1[0]), ncx);
            u64 dyy = add2(pack2(p0[1], p1[1]), ncy);
            u64 dzz = add2(pack2(p0[2], p1[2]), ncz);
            u64 dd  = add2(add2(mul2(dxx, dxx), mul2(dyy, dyy)), mul2(dzz, dzz));
            unpack2(d[2 * kk], d[2 * kk + 1], dd);
        }
        float m = d[0];
        #pragma unroll
        for (int k = 1; k < 16; ++k) m = fminf(m, d[k]);
        int s = 15;
        #pragma unroll
        for (int k = 14; k >= 0; --k)
            if (d[k] == m) s = k;

        out[half + o]            = m;                 // dist2
        out[3 * half + o]        = (float)(r0 + s);   // idx2
    }
}

// ---------------------------------------------------------------- launch
extern "C" void kernel_launch(void* const* d_in, const int* in_sizes, int n_in,
                              void* d_out, int out_size)
{
    const float* xyz1 = (const float*)d_in[0];  // [4, 8192, 3]
    const float* xyz2 = (const float*)d_in[1];  // [4, 8192, 3]
    float* out = (float*)d_out;

    init_kernel<<<(BATCH * NPTS + 255) / 256, 256>>>();

    dim3 grid(NPTS / TC, NPTS / TR, BATCH);   // (64, 64, 4)
    tile_kernel<<<grid, TB>>>(xyz1, xyz2);

    finalize_kernel<<<(2 * BATCH * NPTS) / 128, 128>>>(xyz1, xyz2, out);
}